// round 4
// baseline (speedup 1.0000x reference)
#include <cuda_runtime.h>
#include <math.h>

#define KCODES 512
#define DDIM   64
#define HDIM   64
#define LN_EPS 1e-5f

#define VT     32      // token-values per dist block
#define CHUNK  64      // codes per dist block
#define NCHUNK 8       // 512 / 64
#define VTILES 16      // 512 / 32

// device scratch / LUTs (zero-initialized at module load)
__device__ float  g_q_lut[KCODES * DDIM];     // chosen codebook row per v
__device__ float  g_idx_f[KCODES];            // argmin index per v, as float
__device__ double g_err_lut[KCODES];          // ||cb[idx]-z_v||^2
__device__ int    g_cnt[KCODES];              // histogram of t
__device__ float  g_z[KCODES * DDIM];         // encoder output per v
__device__ float  g_pd[KCODES * NCHUNK];      // partial best dist per (v,chunk)
__device__ int    g_pi[KCODES * NCHUNK];      // partial best idx  per (v,chunk)
__device__ int    g_tile_cnt[VTILES];         // dist last-block tickets
__device__ int    g_sc_ticket;                // scatter last-block ticket

// ---------------------------------------------------------------------------
// Kernel 1: fused encoder + tiled distance/argmin + (last block per v-tile)
// LUT fill. Block = (v-tile of 32 values) x (code chunk of 64). 256 threads.
// All fp32 accumulation orders identical to the round-2/3 kernels that match
// the reference (sequential ascending loops, strict-< first-index tie-break).
// ---------------------------------------------------------------------------
__global__ void dist_kernel(const float* __restrict__ W1,
                            const float* __restrict__ b1,
                            const float* __restrict__ lng,
                            const float* __restrict__ lnb,
                            const float* __restrict__ W2,
                            const float* __restrict__ b2,
                            const float* __restrict__ cb) {
    __shared__ float h_sh[VT * 65];
    __shared__ float z_sh[VT * 65];
    __shared__ float cb_sh[CHUNK * DDIM];     // 16 KB, broadcast reads only
    __shared__ float s_mu[VT], s_rs[VT], s_z2[VT], s_e2[CHUNK];
    __shared__ float s_pd[VT * NCHUNK];
    __shared__ int   s_pi[VT * NCHUNK];
    __shared__ int   s_last;
    __shared__ int   s_bestv[VT];

    const int tid   = threadIdx.x;            // 0..255
    const int vtile = blockIdx.x / NCHUNK;
    const int chunk = blockIdx.x % NCHUNK;
    const int v0    = vtile * VT;
    const int k0    = chunk * CHUNK;

    // ---- h = norm*W1 + b1 for 32 values ----
    for (int idx = tid; idx < VT * HDIM; idx += 256) {
        const int vl = idx >> 6, j = idx & 63;
        const float norm = ((float)(v0 + vl) / (float)(KCODES - 1)) * 2.0f - 1.0f;
        h_sh[vl * 65 + j] = norm * W1[j] + b1[j];
    }
    __syncthreads();

    // ---- LN stats ----
    if (tid < VT) {
        float s = 0.0f;
        for (int j = 0; j < HDIM; j++) s += h_sh[tid * 65 + j];
        const float mu = s / (float)HDIM;
        float vs = 0.0f;
        for (int j = 0; j < HDIM; j++) {
            const float d = h_sh[tid * 65 + j] - mu;
            vs += d * d;
        }
        s_mu[tid] = mu;
        s_rs[tid] = 1.0f / sqrtf(vs / (float)HDIM + LN_EPS);
    }
    __syncthreads();

    // ---- LN + relu ----
    for (int idx = tid; idx < VT * HDIM; idx += 256) {
        const int vl = idx >> 6, j = idx & 63;
        float x = (h_sh[vl * 65 + j] - s_mu[vl]) * s_rs[vl] * lng[j] + lnb[j];
        h_sh[vl * 65 + j] = fmaxf(x, 0.0f);
    }
    __syncthreads();

    // ---- z = h @ W2 + b2 ----
    for (int idx = tid; idx < VT * DDIM; idx += 256) {
        const int vl = idx >> 6, d = idx & 63;
        float acc = 0.0f;
        for (int j = 0; j < HDIM; j++)
            acc += h_sh[vl * 65 + j] * W2[j * DDIM + d];
        z_sh[vl * 65 + d] = acc + b2[d];
    }
    __syncthreads();

    // ---- z2 ----
    if (tid < VT) {
        float s = 0.0f;
        for (int d = 0; d < DDIM; d++) {
            const float zz = z_sh[tid * 65 + d];
            s += zz * zz;
        }
        s_z2[tid] = s;
    }

    // ---- stage codebook chunk (coalesced float4) ----
    {
        const float4* src = reinterpret_cast<const float4*>(cb + (size_t)k0 * DDIM);
        float4* dst = reinterpret_cast<float4*>(cb_sh);
        for (int j = tid; j < CHUNK * (DDIM / 4); j += 256) dst[j] = src[j];
    }

    // ---- e2 per code ----
    if (tid < CHUNK) {
        const float4* e = reinterpret_cast<const float4*>(cb + (size_t)(k0 + tid) * DDIM);
        float acc = 0.0f;
        #pragma unroll
        for (int i = 0; i < DDIM / 4; i++) {
            const float4 c = e[i];
            acc += c.x * c.x;
            acc += c.y * c.y;
            acc += c.z * c.z;
            acc += c.w * c.w;
        }
        s_e2[tid] = acc;
    }

    __syncthreads();
    // chunk==0 blocks persist z (must be globally visible before the ticket)
    if (chunk == 0) {
        for (int idx = tid; idx < VT * DDIM; idx += 256) {
            const int vl = idx >> 6, d = idx & 63;
            g_z[(v0 + vl) * DDIM + d] = z_sh[vl * 65 + d];
        }
    }

    // ---- main: thread (vl, kg) handles 8 contiguous codes ----
    const int vl = tid & 31;
    const int kg = tid >> 5;

    float z[DDIM];
    #pragma unroll
    for (int d = 0; d < DDIM; d++) z[d] = z_sh[vl * 65 + d];
    const float z2 = s_z2[vl];

    float bestD = INFINITY;
    int   bestI = 0;
    for (int c = 0; c < 8; c++) {
        const int kl = kg * 8 + c;
        const float4* e = reinterpret_cast<const float4*>(cb_sh + kl * DDIM);
        float dot = 0.0f;
        #pragma unroll
        for (int i = 0; i < DDIM / 4; i++) {
            const float4 cc = e[i];
            dot += z[4 * i + 0] * cc.x;
            dot += z[4 * i + 1] * cc.y;
            dot += z[4 * i + 2] * cc.z;
            dot += z[4 * i + 3] * cc.w;
        }
        const float dist = z2 - 2.0f * dot + s_e2[kl];
        if (dist < bestD) { bestD = dist; bestI = k0 + kl; }  // strict <, ascending k
    }
    s_pd[vl * NCHUNK + kg] = bestD;
    s_pi[vl * NCHUNK + kg] = bestI;
    __syncthreads();

    // combine across kg in ascending order, publish chunk partials
    if (tid < VT) {
        float bd = INFINITY;
        int   bi = 0;
        for (int g = 0; g < NCHUNK; g++) {
            const float d2 = s_pd[tid * NCHUNK + g];
            if (d2 < bd) { bd = d2; bi = s_pi[tid * NCHUNK + g]; }
        }
        g_pd[(v0 + tid) * NCHUNK + chunk] = bd;
        g_pi[(v0 + tid) * NCHUNK + chunk] = bi;
    }

    // ---- last-block-per-vtile: combine chunks, fill LUTs ----
    __threadfence();
    if (tid == 0) {
        const int ticket = atomicAdd(&g_tile_cnt[vtile], 1);
        s_last = (ticket == NCHUNK - 1) ? 1 : 0;
    }
    __syncthreads();
    if (!s_last) return;
    __threadfence();   // make other blocks' g_pd/g_pi/g_z reads safe

    if (tid < VT) {
        const int v = v0 + tid;
        float bd = INFINITY;
        int   bi = 0;
        for (int c = 0; c < NCHUNK; c++) {        // ascending chunk = ascending k
            const float d = g_pd[v * NCHUNK + c];
            if (d < bd) { bd = d; bi = g_pi[v * NCHUNK + c]; }
        }
        s_bestv[tid] = bi;
        g_idx_f[v]   = (float)bi;
        g_cnt[v]     = 0;                          // reset histogram for scatter

        // double error, 4-way split accumulation
        const float* e  = cb + (size_t)bi * DDIM;
        const float* zp = g_z + v * DDIM;
        double a0 = 0.0, a1 = 0.0, a2 = 0.0, a3 = 0.0;
        for (int d = 0; d < DDIM; d += 4) {
            const double f0 = (double)e[d + 0] - (double)zp[d + 0];
            const double f1 = (double)e[d + 1] - (double)zp[d + 1];
            const double f2 = (double)e[d + 2] - (double)zp[d + 2];
            const double f3 = (double)e[d + 3] - (double)zp[d + 3];
            a0 += f0 * f0; a1 += f1 * f1; a2 += f2 * f2; a3 += f3 * f3;
        }
        g_err_lut[v] = (a0 + a1) + (a2 + a3);
    }
    __syncthreads();

    // fill q LUT (2048 floats, 8 per thread)
    for (int idx = tid; idx < VT * DDIM; idx += 256) {
        const int vvl = idx >> 6, d = idx & 63;
        g_q_lut[(v0 + vvl) * DDIM + d] = cb[(size_t)s_bestv[vvl] * DDIM + d];
    }
    if (tid == 0) g_tile_cnt[vtile] = 0;          // clean for next graph replay
}

// ---------------------------------------------------------------------------
// Kernel 2: scatter + fused histogram + (last block) loss finalize.
// One thread per output float4, unroll 8 load-batch/store-batch.
// ---------------------------------------------------------------------------
#define SC_UNROLL 8
__global__ void scatter_kernel(const int* __restrict__ t,
                               float4* __restrict__ q_out,
                               float* __restrict__ idx_out,
                               float* __restrict__ loss_out, int n) {
    __shared__ int sc[KCODES];
    for (int i = threadIdx.x; i < KCODES; i += blockDim.x) sc[i] = 0;
    __syncthreads();

    const int total  = n * 16;
    const int stride = gridDim.x * blockDim.x;
    const int i0     = blockIdx.x * blockDim.x + threadIdx.x;
    const float4* lut = reinterpret_cast<const float4*>(g_q_lut);

    int    vs[SC_UNROLL];
    float4 vals[SC_UNROLL];

    #pragma unroll
    for (int j = 0; j < SC_UNROLL; j++) {
        const int i = i0 + j * stride;
        if (i < total) {
            const int v = __ldg(t + (i >> 4));
            vs[j]   = v;
            vals[j] = __ldg(&lut[(v << 4) + (i & 15)]);
        } else {
            vs[j] = -1;
        }
    }

    #pragma unroll
    for (int j = 0; j < SC_UNROLL; j++) {
        const int i = i0 + j * stride;
        if (vs[j] >= 0) {
            __stcs(&q_out[i], vals[j]);
            if ((i & 15) == 0) {
                if (idx_out != nullptr) __stcs(&idx_out[i >> 4], g_idx_f[vs[j]]);
                atomicAdd(&sc[vs[j]], 1);
            }
        }
    }

    __syncthreads();
    for (int j = threadIdx.x; j < KCODES; j += blockDim.x) {
        const int c = sc[j];
        if (c) atomicAdd(&g_cnt[j], c);
    }

    // ---- last block computes the loss from the completed histogram ----
    __shared__ int s_last;
    __threadfence();
    if (threadIdx.x == 0) {
        const int ticket = atomicAdd(&g_sc_ticket, 1);
        s_last = (ticket == (int)gridDim.x - 1) ? 1 : 0;
    }
    __syncthreads();
    if (!s_last) return;
    __threadfence();
    if (threadIdx.x == 0) g_sc_ticket = 0;        // clean for next graph replay
    if (loss_out == nullptr) return;

    __shared__ double dacc[256];
    const int tid = threadIdx.x;
    dacc[tid] = (double)g_cnt[tid]       * g_err_lut[tid]
              + (double)g_cnt[tid + 256] * g_err_lut[tid + 256];
    __syncthreads();
    for (int off = 128; off > 0; off >>= 1) {
        if (tid < off) dacc[tid] += dacc[tid + off];
        __syncthreads();
    }
    if (tid == 0) {
        loss_out[0] = (float)(1.25 * dacc[0] / ((double)n * (double)DDIM));
    }
}

// ---------------------------------------------------------------------------
extern "C" void kernel_launch(void* const* d_in, const int* in_sizes, int n_in,
                              void* d_out, int out_size) {
    const int*   t    = (const int*)d_in[0];
    const float* W1   = (const float*)d_in[1];
    const float* b1   = (const float*)d_in[2];
    const float* lng  = (const float*)d_in[3];
    const float* lnb  = (const float*)d_in[4];
    const float* W2   = (const float*)d_in[5];
    const float* b2   = (const float*)d_in[6];
    const float* cb   = (const float*)d_in[7];

    const int n = in_sizes[0];                 // N = B*T = 262144 tokens
    float* out = (float*)d_out;

    // Output layout: [ q : n*64 floats | idx : n floats | loss : 1 float ]
    const bool full = (out_size >= n * DDIM + n + 1);
    float* q_out    = out;
    float* idx_out  = full ? (out + (size_t)n * DDIM) : nullptr;
    float* loss_out = full ? (out + (size_t)n * DDIM + n) : nullptr;

    dist_kernel<<<VTILES * NCHUNK, 256>>>(W1, b1, lng, lnb, W2, b2, cb);

    const int total   = n * 16;
    const int threads = 256;
    const int blocks  = (total + threads * SC_UNROLL - 1) / (threads * SC_UNROLL);
    scatter_kernel<<<blocks, threads>>>(t, (float4*)q_out, idx_out, loss_out, n);
}